// round 2
// baseline (speedup 1.0000x reference)
#include <cuda_runtime.h>
#include <cuda_bf16.h>
#include <math.h>

// Problem constants
#define B_  2
#define T_  2048
#define D_  1024
#define H_  16
#define HS_ 64
#define M_  (B_ * T_)        // 4096 rows for projections

// Scratch (device globals; no allocation allowed)
__device__ float g_q[B_ * H_ * T_ * HS_];   // [B,H,T,HS]
__device__ float g_k[B_ * H_ * T_ * HS_];
__device__ float g_v[B_ * H_ * T_ * HS_];
__device__ float g_y[B_ * T_ * D_];         // [B,T,H*HS]

// ---------------------------------------------------------------------------
// Tiled SGEMM: out = x @ W + bias,  M=4096, N=1024, K=1024
// BM=BN=64, BK=16, 256 threads, 4x4 microtile per thread.
// qkv variant writes into [B,H,T,HS] layout (BN==HS so each block column = 1 head)
// ---------------------------------------------------------------------------
#define BM 64
#define BN 64
#define BK 16

__global__ void __launch_bounds__(256) qkv_gemm(
    const float* __restrict__ x,
    const float* __restrict__ Wq, const float* __restrict__ bq,
    const float* __restrict__ Wk, const float* __restrict__ bk,
    const float* __restrict__ Wv, const float* __restrict__ bv)
{
    const int z = blockIdx.z;
    const float* W    = (z == 0) ? Wq : (z == 1) ? Wk : Wv;
    const float* bias = (z == 0) ? bq : (z == 1) ? bk : bv;
    float* outp       = (z == 0) ? g_q : (z == 1) ? g_k : g_v;

    __shared__ float As[BK][BM];   // transposed (k-major)
    __shared__ float Bs[BK][BN];

    const int tid = threadIdx.x;
    const int tx = tid & 15;       // 0..15  (n direction)
    const int ty = tid >> 4;       // 0..15  (m direction)
    const int m0 = blockIdx.y * BM;
    const int n0 = blockIdx.x * BN;

    // load-index precompute
    const int arow = tid >> 2;            // 0..63
    const int akg  = (tid & 3) * 4;       // k offset {0,4,8,12}
    const int brow = tid >> 6;            // 0..3  -> 4 rows per pass? (16 rows, 4 passes? no:)
    // B tile: 16 rows x 64 cols = 1024 floats = 256 float4; one float4 per thread
    const int b_r  = tid >> 4;            // 0..15 row
    const int b_c  = (tid & 15) * 4;      // col group

    float acc[4][4];
#pragma unroll
    for (int i = 0; i < 4; i++)
#pragma unroll
        for (int j = 0; j < 4; j++) acc[i][j] = 0.f;

    for (int k0 = 0; k0 < D_; k0 += BK) {
        // A tile 64x16 -> transposed into As
        float4 a4 = *(const float4*)&x[(size_t)(m0 + arow) * D_ + k0 + akg];
        As[akg + 0][arow] = a4.x;
        As[akg + 1][arow] = a4.y;
        As[akg + 2][arow] = a4.z;
        As[akg + 3][arow] = a4.w;
        // B tile 16x64
        *(float4*)&Bs[b_r][b_c] = *(const float4*)&W[(size_t)(k0 + b_r) * D_ + n0 + b_c];
        __syncthreads();

#pragma unroll
        for (int kk = 0; kk < BK; kk++) {
            float4 av = *(const float4*)&As[kk][ty * 4];
            float4 bv4 = *(const float4*)&Bs[kk][tx * 4];
            float ar[4] = {av.x, av.y, av.z, av.w};
            float br[4] = {bv4.x, bv4.y, bv4.z, bv4.w};
#pragma unroll
            for (int i = 0; i < 4; i++)
#pragma unroll
                for (int j = 0; j < 4; j++) acc[i][j] += ar[i] * br[j];
        }
        __syncthreads();
    }

    // epilogue: write to [B,H,T,HS]
#pragma unroll
    for (int i = 0; i < 4; i++) {
        int m = m0 + ty * 4 + i;
        int b = m >> 11;          // /T_
        int t = m & (T_ - 1);
#pragma unroll
        for (int j = 0; j < 4; j++) {
            int n = n0 + tx * 4 + j;
            int h = n >> 6;       // /HS_
            int d = n & (HS_ - 1);
            float val = acc[i][j] + bias[n];
            outp[(((size_t)(b * H_ + h)) * T_ + t) * HS_ + d] = val;
        }
    }
}

__global__ void __launch_bounds__(256) out_gemm(
    const float* __restrict__ Wo, const float* __restrict__ bo,
    float* __restrict__ C)
{
    __shared__ float As[BK][BM];
    __shared__ float Bs[BK][BN];

    const int tid = threadIdx.x;
    const int tx = tid & 15;
    const int ty = tid >> 4;
    const int m0 = blockIdx.y * BM;
    const int n0 = blockIdx.x * BN;

    const int arow = tid >> 2;
    const int akg  = (tid & 3) * 4;
    const int b_r  = tid >> 4;
    const int b_c  = (tid & 15) * 4;

    float acc[4][4];
#pragma unroll
    for (int i = 0; i < 4; i++)
#pragma unroll
        for (int j = 0; j < 4; j++) acc[i][j] = 0.f;

    for (int k0 = 0; k0 < D_; k0 += BK) {
        float4 a4 = *(const float4*)&g_y[(size_t)(m0 + arow) * D_ + k0 + akg];
        As[akg + 0][arow] = a4.x;
        As[akg + 1][arow] = a4.y;
        As[akg + 2][arow] = a4.z;
        As[akg + 3][arow] = a4.w;
        *(float4*)&Bs[b_r][b_c] = *(const float4*)&Wo[(size_t)(k0 + b_r) * D_ + n0 + b_c];
        __syncthreads();

#pragma unroll
        for (int kk = 0; kk < BK; kk++) {
            float4 av = *(const float4*)&As[kk][ty * 4];
            float4 bv4 = *(const float4*)&Bs[kk][tx * 4];
            float ar[4] = {av.x, av.y, av.z, av.w};
            float br[4] = {bv4.x, bv4.y, bv4.z, bv4.w};
#pragma unroll
            for (int i = 0; i < 4; i++)
#pragma unroll
                for (int j = 0; j < 4; j++) acc[i][j] += ar[i] * br[j];
        }
        __syncthreads();
    }

#pragma unroll
    for (int i = 0; i < 4; i++) {
        int m = m0 + ty * 4 + i;
#pragma unroll
        for (int j = 0; j < 4; j++) {
            int n = n0 + tx * 4 + j;
            C[(size_t)m * D_ + n] = acc[i][j] + bo[n];
        }
    }
}

// ---------------------------------------------------------------------------
// RoPE in-place on g_q / g_k. One thread per (bh, t, i<32) pair.
// out[i]    = x[i]*cos - x[i+32]*sin
// out[i+32] = x[i+32]*cos + x[i]*sin      (cos/sin index = i mod 32)
// ---------------------------------------------------------------------------
__global__ void __launch_bounds__(256) rope_kernel()
{
    int idx = blockIdx.x * blockDim.x + threadIdx.x;  // < B*H*T*32 = 2097152
    float* arr = (blockIdx.z == 0) ? g_q : g_k;
    int i  = idx & 31;
    int t  = (idx >> 5) & (T_ - 1);
    int bh = idx >> 16;                               // 5 + 11 bits

    // inv_freq = 10000^(-i/32); -log2(10000)/32 = -0.41524101186
    float invf = exp2f((float)i * -0.41524101186091056f);
    float ang = (float)t * invf;
    float s, c;
    sincosf(ang, &s, &c);

    float* p = arr + ((size_t)bh * T_ + t) * HS_;
    float x1 = p[i];
    float x2 = p[i + 32];
    p[i]      = x1 * c - x2 * s;
    p[i + 32] = x2 * c + x1 * s;
}

// ---------------------------------------------------------------------------
// Flash-attention (fp32, online softmax).
// Block: 128 threads, 64 q-rows (2 threads/row: one per 32-wide half).
// Q rows in registers; K tile / transposed-P share one smem array (union);
// V tile separate. Grid: (T/64, B*H); block qi processes k-tiles 0..qi.
// ---------------------------------------------------------------------------
__global__ void __launch_bounds__(128) attn_kernel(const int* __restrict__ amask)
{
    __shared__ float KP[64][64];   // K tile (k-rows x dims), later P^T (kc x qr)
    __shared__ float Vs[64][64];

    const int bh = blockIdx.y;
    const int b  = bh >> 4;
    const int qi = blockIdx.x;
    const int q0 = qi << 6;

    const int tid   = threadIdx.x;
    const int qr    = tid >> 1;     // 0..63
    const int half  = tid & 1;
    const int kcb   = half << 5;    // score columns owned: kcb..kcb+31
    const int dbase = half << 5;    // output dims owned:  dbase..dbase+31
    const int qg    = q0 + qr;

    // Q row into registers
    const float* qrow = g_q + ((size_t)bh * T_ + qg) * HS_;
    float4 qreg[16];
#pragma unroll
    for (int i = 0; i < 16; i++) qreg[i] = ((const float4*)qrow)[i];

    float mrow = -1e30f, lrow = 0.f;
    float4 yacc[8];
#pragma unroll
    for (int i = 0; i < 8; i++) yacc[i] = make_float4(0.f, 0.f, 0.f, 0.f);

    const float* kbase0 = g_k + (size_t)bh * T_ * HS_;
    const float* vbase0 = g_v + (size_t)bh * T_ * HS_;
    const int* mptr = amask + b * T_;

    for (int kt = 0; kt <= qi; kt++) {
        const int k0t = kt << 6;
        __syncthreads();   // previous PV reads done before overwrite

        // cooperative tile load (1024 float4 slots each, 8 per thread)
        const float4* ksrc = (const float4*)(kbase0 + (size_t)k0t * HS_);
        const float4* vsrc = (const float4*)(vbase0 + (size_t)k0t * HS_);
        float4* kdst = (float4*)&KP[0][0];
        float4* vdst = (float4*)&Vs[0][0];
#pragma unroll
        for (int s = 0; s < 8; s++) {
            kdst[tid + s * 128] = ksrc[tid + s * 128];
            vdst[tid + s * 128] = vsrc[tid + s * 128];
        }
        __syncthreads();

        // scores: sc[j] = Q[qr] . K[kcb+j]
        float sc[32];
#pragma unroll
        for (int jg = 0; jg < 8; jg++) {
            float s0 = 0.f, s1 = 0.f, s2 = 0.f, s3 = 0.f;
#pragma unroll
            for (int d4 = 0; d4 < 16; d4++) {
                float4 q4 = qreg[d4];
                float4 k0v = *(const float4*)&KP[kcb + jg * 4 + 0][d4 * 4];
                float4 k1v = *(const float4*)&KP[kcb + jg * 4 + 1][d4 * 4];
                float4 k2v = *(const float4*)&KP[kcb + jg * 4 + 2][d4 * 4];
                float4 k3v = *(const float4*)&KP[kcb + jg * 4 + 3][d4 * 4];
                s0 += q4.x * k0v.x + q4.y * k0v.y + q4.z * k0v.z + q4.w * k0v.w;
                s1 += q4.x * k1v.x + q4.y * k1v.y + q4.z * k1v.z + q4.w * k1v.w;
                s2 += q4.x * k2v.x + q4.y * k2v.y + q4.z * k2v.z + q4.w * k2v.w;
                s3 += q4.x * k3v.x + q4.y * k3v.y + q4.z * k3v.z + q4.w * k3v.w;
            }
            sc[jg * 4 + 0] = s0;
            sc[jg * 4 + 1] = s1;
            sc[jg * 4 + 2] = s2;
            sc[jg * 4 + 3] = s3;
        }
        __syncthreads();   // all K reads done before P^T writes into KP

        // mask + scale + tile max
        float tmax = -1e30f;
#pragma unroll
        for (int j = 0; j < 32; j++) {
            int kgl = k0t + kcb + j;
            bool keep = (kgl <= qg) && (mptr[kgl] != 0);
            sc[j] = keep ? sc[j] * 0.125f : -1e30f;
            tmax = fmaxf(tmax, sc[j]);
        }
        tmax = fmaxf(tmax, __shfl_xor_sync(0xffffffffu, tmax, 1));
        float mnew = fmaxf(mrow, tmax);
        float corr = __expf(mrow - mnew);

        float tsum = 0.f;
#pragma unroll
        for (int j = 0; j < 32; j++) {
            float p = (sc[j] < -1e29f) ? 0.f : __expf(sc[j] - mnew);
            tsum += p;
            KP[kcb + j][qr] = p;    // P^T: row = kc, col = qr (warp-private cols)
        }
        tsum += __shfl_xor_sync(0xffffffffu, tsum, 1);
        lrow = lrow * corr + tsum;
        mrow = mnew;
#pragma unroll
        for (int i = 0; i < 8; i++) {
            yacc[i].x *= corr; yacc[i].y *= corr;
            yacc[i].z *= corr; yacc[i].w *= corr;
        }
        __syncwarp();   // P^T columns are warp-private; warp sync suffices

        // PV: y[qr][d] += sum_j P[qr][j] * V[j][d]
#pragma unroll 4
        for (int j = 0; j < 64; j++) {
            float p = KP[j][qr];
#pragma unroll
            for (int i = 0; i < 8; i++) {
                float4 v4 = *(const float4*)&Vs[j][dbase + i * 4];
                yacc[i].x += p * v4.x;
                yacc[i].y += p * v4.y;
                yacc[i].z += p * v4.z;
                yacc[i].w += p * v4.w;
            }
        }
    }

    // normalize + write y[b][t][h*64 + d]
    float inv = 1.f / lrow;
    float* yout = g_y + ((size_t)b * T_ + qg) * D_ + (bh & 15) * HS_ + dbase;
#pragma unroll
    for (int i = 0; i < 8; i++) {
        float4 o = yacc[i];
        o.x *= inv; o.y *= inv; o.z *= inv; o.w *= inv;
        ((float4*)yout)[i] = o;
    }
}

// ---------------------------------------------------------------------------
extern "C" void kernel_launch(void* const* d_in, const int* in_sizes, int n_in,
                              void* d_out, int out_size)
{
    const float* x   = (const float*)d_in[0];
    const int* amask = (const int*)d_in[1];
    const float* Wq  = (const float*)d_in[2];
    const float* bq  = (const float*)d_in[3];
    const float* Wk  = (const float*)d_in[4];
    const float* bk  = (const float*)d_in[5];
    const float* Wv  = (const float*)d_in[6];
    const float* bv  = (const float*)d_in[7];
    const float* Wo  = (const float*)d_in[8];
    const float* bo  = (const float*)d_in[9];
    float* out = (float*)d_out;

    dim3 gq(D_ / BN, M_ / BM, 3);          // (16, 64, 3)
    qkv_gemm<<<gq, 256>>>(x, Wq, bq, Wk, bk, Wv, bv);

    dim3 gr((B_ * H_ * T_ * 32) / 256, 1, 2);  // (8192, 1, 2)
    rope_kernel<<<gr, 256>>>();

    dim3 ga(T_ / 64, B_ * H_);             // (32, 32)
    attn_kernel<<<ga, 128>>>(amask);

    dim3 go(D_ / BN, M_ / BM);             // (16, 64)
    out_gemm<<<go, 256>>>(Wo, bo, out);
}

// round 4
// speedup vs baseline: 2.3781x; 2.3781x over previous
#include <cuda_runtime.h>
#include <cuda_bf16.h>
#include <math.h>
#include <cstdint>

// Problem constants
#define B_  2
#define T_  2048
#define D_  1024
#define H_  16
#define HS_ 64
#define M_  (B_ * T_)        // 4096 rows for projections

// ---------------------------------------------------------------------------
// Scratch (device globals; no allocation allowed)
// ---------------------------------------------------------------------------
__device__ float g_q[B_ * H_ * T_ * HS_];   // [B,H,T,HS]
__device__ float g_k[B_ * H_ * T_ * HS_];
__device__ float g_v[B_ * H_ * T_ * HS_];
__device__ float g_y[B_ * T_ * D_];         // [B,T,H*HS] (tf32-rounded by attn epilogue)
__device__ float g_xt[M_ * D_];             // x, tf32-rounded
__device__ float g_wt[4 * D_ * D_];         // Wq,Wk,Wv,Wo transposed [N][K], tf32-rounded

// ---------------------------------------------------------------------------
// Helpers
// ---------------------------------------------------------------------------
__device__ __forceinline__ uint32_t smem_to_u32(const void* p) {
    uint32_t a;
    asm("{ .reg .u64 t; cvta.to.shared.u64 t, %1; cvt.u32.u64 %0, t; }" : "=r"(a) : "l"(p));
    return a;
}
__device__ __forceinline__ float rna_tf32(float v) {
    float r;
    asm("cvt.rna.tf32.f32 %0, %1;" : "=f"(r) : "f"(v));
    return r;
}
__device__ __forceinline__ void cp_async16(uint32_t saddr, const void* gptr) {
    asm volatile("cp.async.ca.shared.global [%0], [%1], 16;" :: "r"(saddr), "l"(gptr) : "memory");
}
__device__ __forceinline__ void cp_commit() {
    asm volatile("cp.async.commit_group;" ::: "memory");
}
__device__ __forceinline__ void cp_wait0() {
    asm volatile("cp.async.wait_group 0;" ::: "memory");
}
__device__ __forceinline__ void cp_wait1() {
    asm volatile("cp.async.wait_group 1;" ::: "memory");
}

// mma.sync m16n8k8 tf32 (row.col), D += A*B
__device__ __forceinline__ void mma_tf32(float* d, uint32_t a0, uint32_t a1, uint32_t a2,
                                         uint32_t a3, uint32_t b0, uint32_t b1) {
    asm volatile(
        "mma.sync.aligned.m16n8k8.row.col.f32.tf32.tf32.f32 "
        "{%0,%1,%2,%3}, {%4,%5,%6,%7}, {%8,%9}, {%0,%1,%2,%3};"
        : "+f"(d[0]), "+f"(d[1]), "+f"(d[2]), "+f"(d[3])
        : "r"(a0), "r"(a1), "r"(a2), "r"(a3), "r"(b0), "r"(b1));
}

// ---------------------------------------------------------------------------
// tf32 mma.sync GEMM core.
// CTA tile 128x128, 8 warps in 4(m) x 2(n), warp tile 32x64 = 2x8 m16n8k8 frags.
// K-chunk 32, cp.async double buffer. A:[M][K] row-major, Bt:[N][K] row-major.
// SMEM per buffer: A 128x36, B 128x36 floats (stride 36 -> conflict-free LDS).
// ---------------------------------------------------------------------------
#define BKC     32
#define AST     36
#define BUF_FL  (128 * AST)                 // floats per (A or B) tile
#define GSMEM_SZ (2 * 2 * BUF_FL * 4)       // 73728 bytes

__device__ __forceinline__ void gemm_load_chunk(const float* __restrict__ A,
                                                const float* __restrict__ Bt,
                                                uint32_t smem_base, int buf,
                                                int m0, int n0, int k0, int tid)
{
    // A tile: 128 rows x 32 floats = 1024 float4, 4 per thread
#pragma unroll
    for (int i = 0; i < 4; ++i) {
        int f4  = tid + i * 256;
        int row = f4 >> 3;
        int cg  = f4 & 7;
        uint32_t dst = smem_base + ((buf * 2 + 0) * BUF_FL + row * AST + cg * 4) * 4;
        cp_async16(dst, &A[(size_t)(m0 + row) * D_ + k0 + cg * 4]);
    }
#pragma unroll
    for (int i = 0; i < 4; ++i) {
        int f4  = tid + i * 256;
        int row = f4 >> 3;
        int cg  = f4 & 7;
        uint32_t dst = smem_base + ((buf * 2 + 1) * BUF_FL + row * AST + cg * 4) * 4;
        cp_async16(dst, &Bt[(size_t)(n0 + row) * D_ + k0 + cg * 4]);
    }
    cp_commit();
}

// Compute one 32-wide K chunk from buffer `buf` into acc[2][8][4].
__device__ __forceinline__ void gemm_compute_chunk(const uint32_t* __restrict__ smem_u,
                                                   int buf, int wm, int wn,
                                                   int g, int tg, float acc[2][8][4])
{
    const uint32_t* As = smem_u + (buf * 2 + 0) * BUF_FL;
    const uint32_t* Bs = smem_u + (buf * 2 + 1) * BUF_FL;
    const int mb = wm * 32;
    const int nb = wn * 64;

#pragma unroll
    for (int ks = 0; ks < 4; ++ks) {
        const int k0 = ks * 8;
        uint32_t a[2][4];
#pragma unroll
        for (int mt = 0; mt < 2; ++mt) {
            const uint32_t* ap = As + (mb + mt * 16 + g) * AST + k0 + tg;
            a[mt][0] = ap[0];
            a[mt][1] = ap[8 * AST];
            a[mt][2] = ap[4];
            a[mt][3] = ap[8 * AST + 4];
        }
        uint32_t b[8][2];
#pragma unroll
        for (int nt = 0; nt < 8; ++nt) {
            const uint32_t* bp = Bs + (nb + nt * 8 + g) * AST + k0 + tg;
            b[nt][0] = bp[0];
            b[nt][1] = bp[4];
        }
#pragma unroll
        for (int mt = 0; mt < 2; ++mt)
#pragma unroll
            for (int nt = 0; nt < 8; ++nt)
                mma_tf32(acc[mt][nt], a[mt][0], a[mt][1], a[mt][2], a[mt][3],
                         b[nt][0], b[nt][1]);
    }
}

__device__ __forceinline__ void gemm_main(const float* __restrict__ A,
                                          const float* __restrict__ Bt,
                                          uint32_t smem_base, const uint32_t* smem_u,
                                          int m0, int n0, int tid,
                                          int wm, int wn, int g, int tg,
                                          float acc[2][8][4])
{
#pragma unroll
    for (int mt = 0; mt < 2; ++mt)
#pragma unroll
        for (int nt = 0; nt < 8; ++nt)
#pragma unroll
            for (int i = 0; i < 4; ++i) acc[mt][nt][i] = 0.f;

    const int NCH = D_ / BKC;   // 32
    gemm_load_chunk(A, Bt, smem_base, 0, m0, n0, 0, tid);

    for (int c = 0; c < NCH; ++c) {
        if (c + 1 < NCH) {
            gemm_load_chunk(A, Bt, smem_base, (c + 1) & 1, m0, n0, (c + 1) * BKC, tid);
            cp_wait1();
        } else {
            cp_wait0();
        }
        __syncthreads();
        gemm_compute_chunk(smem_u, c & 1, wm, wn, g, tg, acc);
        __syncthreads();
    }
}

// QKV projection: A = g_xt, Bt = g_wt[z], epilogue writes [B,H,T,HS] + bias
__global__ void __launch_bounds__(256) mma_qkv(const float* __restrict__ bq,
                                               const float* __restrict__ bk,
                                               const float* __restrict__ bv)
{
    extern __shared__ float smem_f[];
    uint32_t smem_base = smem_to_u32(smem_f);
    const uint32_t* smem_u = (const uint32_t*)smem_f;

    const int z = blockIdx.z;
    const float* Bt   = g_wt + (size_t)z * (D_ * D_);
    const float* bias = (z == 0) ? bq : (z == 1) ? bk : bv;
    float* outp       = (z == 0) ? g_q : (z == 1) ? g_k : g_v;

    const int m0 = blockIdx.y * 128;
    const int n0 = blockIdx.x * 128;

    const int tid = threadIdx.x;
    const int wid = tid >> 5;
    const int lane = tid & 31;
    const int wm = wid & 3, wn = wid >> 2;
    const int g = lane >> 2, tg = lane & 3;

    float acc[2][8][4];
    gemm_main(g_xt, Bt, smem_base, smem_u, m0, n0, tid, wm, wn, g, tg, acc);

    // epilogue
#pragma unroll
    for (int mt = 0; mt < 2; ++mt) {
#pragma unroll
        for (int half = 0; half < 2; ++half) {
            int m = m0 + wm * 32 + mt * 16 + g + half * 8;
            int b = m >> 11;
            int t = m & (T_ - 1);
#pragma unroll
            for (int nt = 0; nt < 8; ++nt) {
                int n = n0 + wn * 64 + nt * 8 + 2 * tg;
                int h = n >> 6;
                int d = n & 63;
                float v0 = acc[mt][nt][half * 2 + 0] + bias[n];
                float v1 = acc[mt][nt][half * 2 + 1] + bias[n + 1];
                float* dst = outp + (((size_t)(b * H_ + h)) * T_ + t) * HS_ + d;
                *(float2*)dst = make_float2(v0, v1);
            }
        }
    }
}

// Output projection: A = g_y, Bt = g_wt[3], epilogue row-major + bias
__global__ void __launch_bounds__(256) mma_out(const float* __restrict__ bo,
                                               float* __restrict__ C)
{
    extern __shared__ float smem_f[];
    uint32_t smem_base = smem_to_u32(smem_f);
    const uint32_t* smem_u = (const uint32_t*)smem_f;

    const int m0 = blockIdx.y * 128;
    const int n0 = blockIdx.x * 128;

    const int tid = threadIdx.x;
    const int wid = tid >> 5;
    const int lane = tid & 31;
    const int wm = wid & 3, wn = wid >> 2;
    const int g = lane >> 2, tg = lane & 3;

    float acc[2][8][4];
    gemm_main(g_y, g_wt + (size_t)3 * (D_ * D_), smem_base, smem_u,
              m0, n0, tid, wm, wn, g, tg, acc);

#pragma unroll
    for (int mt = 0; mt < 2; ++mt) {
#pragma unroll
        for (int half = 0; half < 2; ++half) {
            int m = m0 + wm * 32 + mt * 16 + g + half * 8;
#pragma unroll
            for (int nt = 0; nt < 8; ++nt) {
                int n = n0 + wn * 64 + nt * 8 + 2 * tg;
                float v0 = acc[mt][nt][half * 2 + 0] + bo[n];
                float v1 = acc[mt][nt][half * 2 + 1] + bo[n + 1];
                *(float2*)&C[(size_t)m * D_ + n] = make_float2(v0, v1);
            }
        }
    }
}

// ---------------------------------------------------------------------------
// Prep: tf32-round x into g_xt
// ---------------------------------------------------------------------------
__global__ void __launch_bounds__(256) round_x_kernel(const float* __restrict__ x)
{
    int i = blockIdx.x * 256 + threadIdx.x;
    float4 v = ((const float4*)x)[i];
    v.x = rna_tf32(v.x); v.y = rna_tf32(v.y);
    v.z = rna_tf32(v.z); v.w = rna_tf32(v.w);
    ((float4*)g_xt)[i] = v;
}

// Transpose + tf32-round the 4 weight matrices: g_wt[z][n][k] = rna(W_z[k][n])
__global__ void __launch_bounds__(256) transpose_w_kernel(
    const float* __restrict__ Wq, const float* __restrict__ Wk,
    const float* __restrict__ Wv, const float* __restrict__ Wo)
{
    __shared__ float t[32][33];
    const int z = blockIdx.z;
    const float* W = (z == 0) ? Wq : (z == 1) ? Wk : (z == 2) ? Wv : Wo;
    float* out = g_wt + (size_t)z * (D_ * D_);

    const int x0 = blockIdx.x * 32;   // n
    const int y0 = blockIdx.y * 32;   // k
    const int tx = threadIdx.x & 31;
    const int ty = threadIdx.x >> 5;  // 0..7

#pragma unroll
    for (int i = 0; i < 4; ++i)
        t[ty + 8 * i][tx] = W[(size_t)(y0 + ty + 8 * i) * D_ + x0 + tx];
    __syncthreads();
#pragma unroll
    for (int i = 0; i < 4; ++i)
        out[(size_t)(x0 + ty + 8 * i) * D_ + y0 + tx] = rna_tf32(t[tx][ty + 8 * i]);
}

// ---------------------------------------------------------------------------
// RoPE in-place on g_q / g_k
// ---------------------------------------------------------------------------
__global__ void __launch_bounds__(256) rope_kernel()
{
    int idx = blockIdx.x * blockDim.x + threadIdx.x;
    float* arr = (blockIdx.z == 0) ? g_q : g_k;
    int i  = idx & 31;
    int t  = (idx >> 5) & (T_ - 1);
    int bh = idx >> 16;

    float invf = exp2f((float)i * -0.41524101186091056f);
    float ang = (float)t * invf;
    float s, c;
    sincosf(ang, &s, &c);

    float* p = arr + ((size_t)bh * T_ + t) * HS_;
    float x1 = p[i];
    float x2 = p[i + 32];
    p[i]      = x1 * c - x2 * s;
    p[i + 32] = x2 * c + x1 * s;
}

// ---------------------------------------------------------------------------
// Flash-attention (fp32, online softmax) — unchanged except tf32-rounded y out
// ---------------------------------------------------------------------------
__global__ void __launch_bounds__(128) attn_kernel(const int* __restrict__ amask)
{
    __shared__ float KP[64][64];
    __shared__ float Vs[64][64];

    const int bh = blockIdx.y;
    const int b  = bh >> 4;
    const int qi = blockIdx.x;
    const int q0 = qi << 6;

    const int tid   = threadIdx.x;
    const int qr    = tid >> 1;
    const int half  = tid & 1;
    const int kcb   = half << 5;
    const int dbase = half << 5;
    const int qg    = q0 + qr;

    const float* qrow = g_q + ((size_t)bh * T_ + qg) * HS_;
    float4 qreg[16];
#pragma unroll
    for (int i = 0; i < 16; i++) qreg[i] = ((const float4*)qrow)[i];

    float mrow = -1e30f, lrow = 0.f;
    float4 yacc[8];
#pragma unroll
    for (int i = 0; i < 8; i++) yacc[i] = make_float4(0.f, 0.f, 0.f, 0.f);

    const float* kbase0 = g_k + (size_t)bh * T_ * HS_;
    const float* vbase0 = g_v + (size_t)bh * T_ * HS_;
    const int* mptr = amask + b * T_;

    for (int kt = 0; kt <= qi; kt++) {
        const int k0t = kt << 6;
        __syncthreads();

        const float4* ksrc = (const float4*)(kbase0 + (size_t)k0t * HS_);
        const float4* vsrc = (const float4*)(vbase0 + (size_t)k0t * HS_);
        float4* kdst = (float4*)&KP[0][0];
        float4* vdst = (float4*)&Vs[0][0];
#pragma unroll
        for (int s = 0; s < 8; s++) {
            kdst[tid + s * 128] = ksrc[tid + s * 128];
            vdst[tid + s * 128] = vsrc[tid + s * 128];
        }
        __syncthreads();

        float sc[32];
#pragma unroll
        for (int jg = 0; jg < 8; jg++) {
            float s0 = 0.f, s1 = 0.f, s2 = 0.f, s3 = 0.f;
#pragma unroll
            for (int d4 = 0; d4 < 16; d4++) {
                float4 q4 = qreg[d4];
                float4 k0v = *(const float4*)&KP[kcb + jg * 4 + 0][d4 * 4];
                float4 k1v = *(const float4*)&KP[kcb + jg * 4 + 1][d4 * 4];
                float4 k2v = *(const float4*)&KP[kcb + jg * 4 + 2][d4 * 4];
                float4 k3v = *(const float4*)&KP[kcb + jg * 4 + 3][d4 * 4];
                s0 += q4.x * k0v.x + q4.y * k0v.y + q4.z * k0v.z + q4.w * k0v.w;
                s1 += q4.x * k1v.x + q4.y * k1v.y + q4.z * k1v.z + q4.w * k1v.w;
                s2 += q4.x * k2v.x + q4.y * k2v.y + q4.z * k2v.z + q4.w * k2v.w;
                s3 += q4.x * k3v.x + q4.y * k3v.y + q4.z * k3v.z + q4.w * k3v.w;
            }
            sc[jg * 4 + 0] = s0;
            sc[jg * 4 + 1] = s1;
            sc[jg * 4 + 2] = s2;
            sc[jg * 4 + 3] = s3;
        }
        __syncthreads();

        float tmax = -1e30f;
#pragma unroll
        for (int j = 0; j < 32; j++) {
            int kgl = k0t + kcb + j;
            bool keep = (kgl <= qg) && (mptr[kgl] != 0);
            sc[j] = keep ? sc[j] * 0.125f : -1e30f;
            tmax = fmaxf(tmax, sc[j]);
        }
        tmax = fmaxf(tmax, __shfl_xor_sync(0xffffffffu, tmax, 1));
        float mnew = fmaxf(mrow, tmax);
        float corr = __expf(mrow - mnew);

        float tsum = 0.f;
#pragma unroll
        for (int j = 0; j < 32; j++) {
            float p = (sc[j] < -1e29f) ? 0.f : __expf(sc[j] - mnew);
            tsum += p;
            KP[kcb + j][qr] = p;
        }
        tsum += __shfl_xor_sync(0xffffffffu, tsum, 1);
        lrow = lrow * corr + tsum;
        mrow = mnew;
#pragma unroll
        for (int i = 0; i < 8; i++) {
            yacc[i].x *= corr; yacc[i].y *= corr;
            yacc[i].z *= corr; yacc[i].w *= corr;
        }
        __syncwarp();

#pragma unroll 4
        for (int j = 0; j < 64; j++) {
            float p = KP[j][qr];
#pragma unroll
            for (int i = 0; i < 8; i++) {
                float4 v4 = *(const float4*)&Vs[j][dbase + i * 4];
                yacc[i].x += p * v4.x;
                yacc[i].y += p * v4.y;
                yacc[i].z += p * v4.z;
                yacc[i].w += p * v4.w;
            }
        }
    }

    // normalize + tf32-round + write y[b][t][h*64 + d]
    float inv = 1.f / lrow;
    float* yout = g_y + ((size_t)b * T_ + qg) * D_ + (bh & 15) * HS_ + dbase;
#pragma unroll
    for (int i = 0; i < 8; i++) {
        float4 o = yacc[i];
        o.x = rna_tf32(o.x * inv); o.y = rna_tf32(o.y * inv);
        o.z = rna_tf32(o.z * inv); o.w = rna_tf32(o.w * inv);
        ((float4*)yout)[i] = o;
    }
}

// ---------------------------------------------------------------------------
extern "C" void kernel_launch(void* const* d_in, const int* in_sizes, int n_in,
                              void* d_out, int out_size)
{
    const float* x   = (const float*)d_in[0];
    const int* amask = (const int*)d_in[1];
    const float* Wq  = (const float*)d_in[2];
    const float* bq  = (const float*)d_in[3];
    const float* Wk  = (const float*)d_in[4];
    const float* bk  = (const float*)d_in[5];
    const float* Wv  = (const float*)d_in[6];
    const float* bv  = (const float*)d_in[7];
    const float* Wo  = (const float*)d_in[8];
    const float* bo  = (const float*)d_in[9];
    float* out = (float*)d_out;

    static bool attr_set = false;
    if (!attr_set) {
        cudaFuncSetAttribute(mma_qkv, cudaFuncAttributeMaxDynamicSharedMemorySize, GSMEM_SZ);
        cudaFuncSetAttribute(mma_out, cudaFuncAttributeMaxDynamicSharedMemorySize, GSMEM_SZ);
        attr_set = true;
    }

    // Prep: round x; transpose+round weights
    round_x_kernel<<<(M_ * D_ / 4) / 256, 256>>>(x);
    transpose_w_kernel<<<dim3(32, 32, 4), 256>>>(Wq, Wk, Wv, Wo);

    // QKV projections (mma.sync tf32)
    mma_qkv<<<dim3(D_ / 128, M_ / 128, 3), 256, GSMEM_SZ>>>(bq, bk, bv);

    // RoPE
    dim3 gr((B_ * H_ * T_ * 32) / 256, 1, 2);
    rope_kernel<<<gr, 256>>>();

    // Attention
    dim3 ga(T_ / 64, B_ * H_);
    attn_kernel<<<ga, 128>>>(amask);

    // Output projection (mma.sync tf32)
    mma_out<<<dim3(D_ / 128, M_ / 128), 256, GSMEM_SZ>>>(bo, out);
}

// round 5
// speedup vs baseline: 4.8684x; 2.0472x over previous
#include <cuda_runtime.h>
#include <cuda_bf16.h>
#include <math.h>
#include <cstdint>

// Problem constants
#define B_  2
#define T_  2048
#define D_  1024
#define H_  16
#define HS_ 64
#define M_  (B_ * T_)        // 4096 rows for projections

// ---------------------------------------------------------------------------
// Scratch (device globals; no allocation allowed)
// ---------------------------------------------------------------------------
__device__ float g_q[B_ * H_ * T_ * HS_];   // [B,H,T,HS] (tf32-rounded after rope)
__device__ float g_k[B_ * H_ * T_ * HS_];
__device__ float g_v[B_ * H_ * T_ * HS_];   // tf32-rounded at qkv epilogue
__device__ float g_y[B_ * T_ * D_];         // [B,T,H*HS] tf32-rounded by attn epilogue
__device__ float g_xt[M_ * D_];             // x, tf32-rounded
__device__ float g_wt[4 * D_ * D_];         // Wq,Wk,Wv,Wo transposed [N][K], tf32-rounded

// ---------------------------------------------------------------------------
// Helpers
// ---------------------------------------------------------------------------
__device__ __forceinline__ uint32_t smem_to_u32(const void* p) {
    uint32_t a;
    asm("{ .reg .u64 t; cvta.to.shared.u64 t, %1; cvt.u32.u64 %0, t; }" : "=r"(a) : "l"(p));
    return a;
}
__device__ __forceinline__ float rna_tf32(float v) {
    float r;
    asm("cvt.rna.tf32.f32 %0, %1;" : "=f"(r) : "f"(v));
    return r;
}
__device__ __forceinline__ void cp_async16(uint32_t saddr, const void* gptr) {
    asm volatile("cp.async.ca.shared.global [%0], [%1], 16;" :: "r"(saddr), "l"(gptr) : "memory");
}
__device__ __forceinline__ void cp_commit() {
    asm volatile("cp.async.commit_group;" ::: "memory");
}
__device__ __forceinline__ void cp_wait0() {
    asm volatile("cp.async.wait_group 0;" ::: "memory");
}
__device__ __forceinline__ void cp_wait1() {
    asm volatile("cp.async.wait_group 1;" ::: "memory");
}

// mma.sync m16n8k8 tf32 (row.col), D += A*B
__device__ __forceinline__ void mma_tf32(float* d, uint32_t a0, uint32_t a1, uint32_t a2,
                                         uint32_t a3, uint32_t b0, uint32_t b1) {
    asm volatile(
        "mma.sync.aligned.m16n8k8.row.col.f32.tf32.tf32.f32 "
        "{%0,%1,%2,%3}, {%4,%5,%6,%7}, {%8,%9}, {%0,%1,%2,%3};"
        : "+f"(d[0]), "+f"(d[1]), "+f"(d[2]), "+f"(d[3])
        : "r"(a0), "r"(a1), "r"(a2), "r"(a3), "r"(b0), "r"(b1));
}

// ---------------------------------------------------------------------------
// tf32 mma.sync GEMM core (projections).
// CTA tile 128x128, 8 warps in 4(m) x 2(n), warp tile 32x64 = 2x8 m16n8k8 frags.
// K-chunk 32, cp.async double buffer. A:[M][K] row-major, Bt:[N][K] row-major.
// ---------------------------------------------------------------------------
#define BKC     32
#define AST     36
#define BUF_FL  (128 * AST)                 // floats per (A or B) tile
#define GSMEM_SZ (2 * 2 * BUF_FL * 4)       // 73728 bytes

__device__ __forceinline__ void gemm_load_chunk(const float* __restrict__ A,
                                                const float* __restrict__ Bt,
                                                uint32_t smem_base, int buf,
                                                int m0, int n0, int k0, int tid)
{
#pragma unroll
    for (int i = 0; i < 4; ++i) {
        int f4  = tid + i * 256;
        int row = f4 >> 3;
        int cg  = f4 & 7;
        uint32_t dst = smem_base + ((buf * 2 + 0) * BUF_FL + row * AST + cg * 4) * 4;
        cp_async16(dst, &A[(size_t)(m0 + row) * D_ + k0 + cg * 4]);
    }
#pragma unroll
    for (int i = 0; i < 4; ++i) {
        int f4  = tid + i * 256;
        int row = f4 >> 3;
        int cg  = f4 & 7;
        uint32_t dst = smem_base + ((buf * 2 + 1) * BUF_FL + row * AST + cg * 4) * 4;
        cp_async16(dst, &Bt[(size_t)(n0 + row) * D_ + k0 + cg * 4]);
    }
    cp_commit();
}

__device__ __forceinline__ void gemm_compute_chunk(const uint32_t* __restrict__ smem_u,
                                                   int buf, int wm, int wn,
                                                   int g, int tg, float acc[2][8][4])
{
    const uint32_t* As = smem_u + (buf * 2 + 0) * BUF_FL;
    const uint32_t* Bs = smem_u + (buf * 2 + 1) * BUF_FL;
    const int mb = wm * 32;
    const int nb = wn * 64;

#pragma unroll
    for (int ks = 0; ks < 4; ++ks) {
        const int k0 = ks * 8;
        uint32_t a[2][4];
#pragma unroll
        for (int mt = 0; mt < 2; ++mt) {
            const uint32_t* ap = As + (mb + mt * 16 + g) * AST + k0 + tg;
            a[mt][0] = ap[0];
            a[mt][1] = ap[8 * AST];
            a[mt][2] = ap[4];
            a[mt][3] = ap[8 * AST + 4];
        }
        uint32_t b[8][2];
#pragma unroll
        for (int nt = 0; nt < 8; ++nt) {
            const uint32_t* bp = Bs + (nb + nt * 8 + g) * AST + k0 + tg;
            b[nt][0] = bp[0];
            b[nt][1] = bp[4];
        }
#pragma unroll
        for (int mt = 0; mt < 2; ++mt)
#pragma unroll
            for (int nt = 0; nt < 8; ++nt)
                mma_tf32(acc[mt][nt], a[mt][0], a[mt][1], a[mt][2], a[mt][3],
                         b[nt][0], b[nt][1]);
    }
}

__device__ __forceinline__ void gemm_main(const float* __restrict__ A,
                                          const float* __restrict__ Bt,
                                          uint32_t smem_base, const uint32_t* smem_u,
                                          int m0, int n0, int tid,
                                          int wm, int wn, int g, int tg,
                                          float acc[2][8][4])
{
#pragma unroll
    for (int mt = 0; mt < 2; ++mt)
#pragma unroll
        for (int nt = 0; nt < 8; ++nt)
#pragma unroll
            for (int i = 0; i < 4; ++i) acc[mt][nt][i] = 0.f;

    const int NCH = D_ / BKC;   // 32
    gemm_load_chunk(A, Bt, smem_base, 0, m0, n0, 0, tid);

    for (int c = 0; c < NCH; ++c) {
        if (c + 1 < NCH) {
            gemm_load_chunk(A, Bt, smem_base, (c + 1) & 1, m0, n0, (c + 1) * BKC, tid);
            cp_wait1();
        } else {
            cp_wait0();
        }
        __syncthreads();
        gemm_compute_chunk(smem_u, c & 1, wm, wn, g, tg, acc);
        __syncthreads();
    }
}

// QKV projection: A = g_xt, Bt = g_wt[z], epilogue writes [B,H,T,HS] + bias
__global__ void __launch_bounds__(256) mma_qkv(const float* __restrict__ bq,
                                               const float* __restrict__ bk,
                                               const float* __restrict__ bv)
{
    extern __shared__ float smem_f[];
    uint32_t smem_base = smem_to_u32(smem_f);
    const uint32_t* smem_u = (const uint32_t*)smem_f;

    const int z = blockIdx.z;
    const float* Bt   = g_wt + (size_t)z * (D_ * D_);
    const float* bias = (z == 0) ? bq : (z == 1) ? bk : bv;
    float* outp       = (z == 0) ? g_q : (z == 1) ? g_k : g_v;

    const int m0 = blockIdx.y * 128;
    const int n0 = blockIdx.x * 128;

    const int tid = threadIdx.x;
    const int wid = tid >> 5;
    const int lane = tid & 31;
    const int wm = wid & 3, wn = wid >> 2;
    const int g = lane >> 2, tg = lane & 3;

    float acc[2][8][4];
    gemm_main(g_xt, Bt, smem_base, smem_u, m0, n0, tid, wm, wn, g, tg, acc);

#pragma unroll
    for (int mt = 0; mt < 2; ++mt) {
#pragma unroll
        for (int half = 0; half < 2; ++half) {
            int m = m0 + wm * 32 + mt * 16 + g + half * 8;
            int b = m >> 11;
            int t = m & (T_ - 1);
#pragma unroll
            for (int nt = 0; nt < 8; ++nt) {
                int n = n0 + wn * 64 + nt * 8 + 2 * tg;
                int h = n >> 6;
                int d = n & 63;
                float v0 = acc[mt][nt][half * 2 + 0] + bias[n];
                float v1 = acc[mt][nt][half * 2 + 1] + bias[n + 1];
                if (z == 2) { v0 = rna_tf32(v0); v1 = rna_tf32(v1); }  // V feeds PV mma
                float* dst = outp + (((size_t)(b * H_ + h)) * T_ + t) * HS_ + d;
                *(float2*)dst = make_float2(v0, v1);
            }
        }
    }
}

// Output projection: A = g_y, Bt = g_wt[3], epilogue row-major + bias
__global__ void __launch_bounds__(256) mma_out(const float* __restrict__ bo,
                                               float* __restrict__ C)
{
    extern __shared__ float smem_f[];
    uint32_t smem_base = smem_to_u32(smem_f);
    const uint32_t* smem_u = (const uint32_t*)smem_f;

    const int m0 = blockIdx.y * 128;
    const int n0 = blockIdx.x * 128;

    const int tid = threadIdx.x;
    const int wid = tid >> 5;
    const int lane = tid & 31;
    const int wm = wid & 3, wn = wid >> 2;
    const int g = lane >> 2, tg = lane & 3;

    float acc[2][8][4];
    gemm_main(g_y, g_wt + (size_t)3 * (D_ * D_), smem_base, smem_u,
              m0, n0, tid, wm, wn, g, tg, acc);

#pragma unroll
    for (int mt = 0; mt < 2; ++mt) {
#pragma unroll
        for (int half = 0; half < 2; ++half) {
            int m = m0 + wm * 32 + mt * 16 + g + half * 8;
#pragma unroll
            for (int nt = 0; nt < 8; ++nt) {
                int n = n0 + wn * 64 + nt * 8 + 2 * tg;
                float v0 = acc[mt][nt][half * 2 + 0] + bo[n];
                float v1 = acc[mt][nt][half * 2 + 1] + bo[n + 1];
                *(float2*)&C[(size_t)m * D_ + n] = make_float2(v0, v1);
            }
        }
    }
}

// ---------------------------------------------------------------------------
// Prep kernels
// ---------------------------------------------------------------------------
__global__ void __launch_bounds__(256) round_x_kernel(const float* __restrict__ x)
{
    int i = blockIdx.x * 256 + threadIdx.x;
    float4 v = ((const float4*)x)[i];
    v.x = rna_tf32(v.x); v.y = rna_tf32(v.y);
    v.z = rna_tf32(v.z); v.w = rna_tf32(v.w);
    ((float4*)g_xt)[i] = v;
}

__global__ void __launch_bounds__(256) transpose_w_kernel(
    const float* __restrict__ Wq, const float* __restrict__ Wk,
    const float* __restrict__ Wv, const float* __restrict__ Wo)
{
    __shared__ float t[32][33];
    const int z = blockIdx.z;
    const float* W = (z == 0) ? Wq : (z == 1) ? Wk : (z == 2) ? Wv : Wo;
    float* out = g_wt + (size_t)z * (D_ * D_);

    const int x0 = blockIdx.x * 32;
    const int y0 = blockIdx.y * 32;
    const int tx = threadIdx.x & 31;
    const int ty = threadIdx.x >> 5;

#pragma unroll
    for (int i = 0; i < 4; ++i)
        t[ty + 8 * i][tx] = W[(size_t)(y0 + ty + 8 * i) * D_ + x0 + tx];
    __syncthreads();
#pragma unroll
    for (int i = 0; i < 4; ++i)
        out[(size_t)(x0 + ty + 8 * i) * D_ + y0 + tx] = rna_tf32(t[tx][ty + 8 * i]);
}

// ---------------------------------------------------------------------------
// RoPE in-place on g_q / g_k, output tf32-rounded (feeds QK^T mma)
// ---------------------------------------------------------------------------
__global__ void __launch_bounds__(256) rope_kernel()
{
    int idx = blockIdx.x * blockDim.x + threadIdx.x;
    float* arr = (blockIdx.z == 0) ? g_q : g_k;
    int i  = idx & 31;
    int t  = (idx >> 5) & (T_ - 1);
    int bh = idx >> 16;

    float invf = exp2f((float)i * -0.41524101186091056f);
    float ang = (float)t * invf;
    float s, c;
    sincosf(ang, &s, &c);

    float* p = arr + ((size_t)bh * T_ + t) * HS_;
    float x1 = p[i];
    float x2 = p[i + 32];
    p[i]      = rna_tf32(x1 * c - x2 * s);
    p[i + 32] = rna_tf32(x2 * c + x1 * s);
}

// ---------------------------------------------------------------------------
// Tensor-core flash attention (tf32 mma.sync, online softmax in fragments).
// CTA: 128 threads = 4 warps; 64 q-rows per CTA (16 per warp); kv tiles of 64.
// SMEM: Ks[64][68] (Q staging then K tile), Vs[64][68], Ps[4][16][68], msk[64].
// ---------------------------------------------------------------------------
#define KVST 68
#define ASMEM_FL (3 * 64 * KVST + 64)
#define ASMEM_SZ (ASMEM_FL * 4)     // 52480 bytes

__global__ void __launch_bounds__(128) attn_mma_kernel(const int* __restrict__ amask)
{
    extern __shared__ float sm[];
    float* Ks  = sm;                     // [64][68]  (Q staging, then K tiles)
    float* Vs  = sm + 64 * KVST;         // [64][68]
    float* Ps  = sm + 2 * 64 * KVST;     // [4][16][68]
    float* msk = sm + 3 * 64 * KVST;     // [64]

    const int bh = blockIdx.y;
    const int b  = bh >> 4;
    const int qi = (int)(gridDim.x - 1) - (int)blockIdx.x;   // big tiles first
    const int q0 = qi << 6;

    const int tid  = threadIdx.x;
    const int wid  = tid >> 5;
    const int lane = tid & 31;
    const int g  = lane >> 2, tg = lane & 3;
    const int mb = wid * 16;

    const float* qbase = g_q + ((size_t)bh * T_ + q0) * HS_;
    const float* kbase = g_k + (size_t)bh * T_ * HS_;
    const float* vbase = g_v + (size_t)bh * T_ * HS_;
    const int* mptr = amask + b * T_;

    // ---- stage Q tile into Ks, pull A-fragments into registers ----
#pragma unroll
    for (int i = 0; i < 8; ++i) {
        int f4 = tid + i * 128;
        int row = f4 >> 4, cg = f4 & 15;
        *(float4*)&Ks[row * KVST + cg * 4] = ((const float4*)qbase)[f4];
    }
    __syncthreads();
    uint32_t qa[8][4];
    {
        const uint32_t* Ku = (const uint32_t*)Ks;
#pragma unroll
        for (int kc = 0; kc < 8; ++kc) {
            qa[kc][0] = Ku[(mb + g) * KVST + kc * 8 + tg];
            qa[kc][1] = Ku[(mb + g + 8) * KVST + kc * 8 + tg];
            qa[kc][2] = Ku[(mb + g) * KVST + kc * 8 + tg + 4];
            qa[kc][3] = Ku[(mb + g + 8) * KVST + kc * 8 + tg + 4];
        }
    }

    float m_g = -1e30f, m_h = -1e30f, l_g = 0.f, l_h = 0.f;
    float oacc[8][4];
#pragma unroll
    for (int nt = 0; nt < 8; ++nt)
#pragma unroll
        for (int i = 0; i < 4; ++i) oacc[nt][i] = 0.f;

    const int qrow_g = q0 + mb + g;
    const int qrow_h = qrow_g + 8;
    float* Pw = Ps + wid * 16 * KVST;
    const uint32_t* Ku = (const uint32_t*)Ks;
    const uint32_t* Vu = (const uint32_t*)Vs;
    const uint32_t* Pu = (const uint32_t*)Pw;

    for (int kt = 0; kt <= qi; ++kt) {
        const int k0t = kt << 6;
        __syncthreads();   // previous tile fully consumed (also guards Q-frag reads)

        const float4* ksrc = (const float4*)(kbase + (size_t)k0t * HS_);
        const float4* vsrc = (const float4*)(vbase + (size_t)k0t * HS_);
#pragma unroll
        for (int i = 0; i < 8; ++i) {
            int f4 = tid + i * 128;
            int row = f4 >> 4, cg = f4 & 15;
            *(float4*)&Ks[row * KVST + cg * 4] = ksrc[f4];
            *(float4*)&Vs[row * KVST + cg * 4] = vsrc[f4];
        }
        if (tid < 64) msk[tid] = (mptr[k0t + tid] != 0) ? 0.f : -1e30f;
        __syncthreads();

        // ---- S = Q K^T ----
        float sacc[8][4];
#pragma unroll
        for (int nt = 0; nt < 8; ++nt)
#pragma unroll
            for (int i = 0; i < 4; ++i) sacc[nt][i] = 0.f;

#pragma unroll
        for (int kc = 0; kc < 8; ++kc) {
            uint32_t bfr[8][2];
#pragma unroll
            for (int nt = 0; nt < 8; ++nt) {
                const uint32_t* bp = Ku + (nt * 8 + g) * KVST + kc * 8 + tg;
                bfr[nt][0] = bp[0];
                bfr[nt][1] = bp[4];
            }
#pragma unroll
            for (int nt = 0; nt < 8; ++nt)
                mma_tf32(sacc[nt], qa[kc][0], qa[kc][1], qa[kc][2], qa[kc][3],
                         bfr[nt][0], bfr[nt][1]);
        }

        // ---- scale + mask + row max ----
        float tmax_g = -1e30f, tmax_h = -1e30f;
#pragma unroll
        for (int nt = 0; nt < 8; ++nt) {
            const int c0 = nt * 8 + 2 * tg, c1 = c0 + 1;
            float mk0 = msk[c0], mk1 = msk[c1];
            float s0 = fmaf(sacc[nt][0], 0.125f, mk0);
            float s1 = fmaf(sacc[nt][1], 0.125f, mk1);
            float s2 = fmaf(sacc[nt][2], 0.125f, mk0);
            float s3 = fmaf(sacc[nt][3], 0.125f, mk1);
            if (kt == qi) {
                if (k0t + c0 > qrow_g) s0 = -1e30f;
                if (k0t + c1 > qrow_g) s1 = -1e30f;
                if (k0t + c0 > qrow_h) s2 = -1e30f;
                if (k0t + c1 > qrow_h) s3 = -1e30f;
            }
            sacc[nt][0] = s0; sacc[nt][1] = s1; sacc[nt][2] = s2; sacc[nt][3] = s3;
            tmax_g = fmaxf(tmax_g, fmaxf(s0, s1));
            tmax_h = fmaxf(tmax_h, fmaxf(s2, s3));
        }
        tmax_g = fmaxf(tmax_g, __shfl_xor_sync(0xffffffffu, tmax_g, 1));
        tmax_g = fmaxf(tmax_g, __shfl_xor_sync(0xffffffffu, tmax_g, 2));
        tmax_h = fmaxf(tmax_h, __shfl_xor_sync(0xffffffffu, tmax_h, 1));
        tmax_h = fmaxf(tmax_h, __shfl_xor_sync(0xffffffffu, tmax_h, 2));

        const float mn_g = fmaxf(m_g, tmax_g);
        const float mn_h = fmaxf(m_h, tmax_h);
        const float corr_g = __expf(m_g - mn_g);
        const float corr_h = __expf(m_h - mn_h);
        m_g = mn_g; m_h = mn_h;

        // ---- exp + row sum + tf32-round P ----
        float rs_g = 0.f, rs_h = 0.f;
#pragma unroll
        for (int nt = 0; nt < 8; ++nt) {
            float p0 = __expf(sacc[nt][0] - mn_g);
            float p1 = __expf(sacc[nt][1] - mn_g);
            float p2 = __expf(sacc[nt][2] - mn_h);
            float p3 = __expf(sacc[nt][3] - mn_h);
            rs_g += p0 + p1;
            rs_h += p2 + p3;
            sacc[nt][0] = rna_tf32(p0); sacc[nt][1] = rna_tf32(p1);
            sacc[nt][2] = rna_tf32(p2); sacc[nt][3] = rna_tf32(p3);
        }
        rs_g += __shfl_xor_sync(0xffffffffu, rs_g, 1);
        rs_g += __shfl_xor_sync(0xffffffffu, rs_g, 2);
        rs_h += __shfl_xor_sync(0xffffffffu, rs_h, 1);
        rs_h += __shfl_xor_sync(0xffffffffu, rs_h, 2);
        l_g = l_g * corr_g + rs_g;
        l_h = l_h * corr_h + rs_h;

#pragma unroll
        for (int nt = 0; nt < 8; ++nt) {
            oacc[nt][0] *= corr_g; oacc[nt][1] *= corr_g;
            oacc[nt][2] *= corr_h; oacc[nt][3] *= corr_h;
        }

        // ---- P accumulator-layout -> A-fragment layout via warp-private smem ----
        __syncwarp();
#pragma unroll
        for (int nt = 0; nt < 8; ++nt) {
            *(float2*)&Pw[g * KVST + nt * 8 + 2 * tg]       = make_float2(sacc[nt][0], sacc[nt][1]);
            *(float2*)&Pw[(g + 8) * KVST + nt * 8 + 2 * tg] = make_float2(sacc[nt][2], sacc[nt][3]);
        }
        __syncwarp();

        // ---- O += P V ----
#pragma unroll
        for (int kc = 0; kc < 8; ++kc) {
            uint32_t pa0 = Pu[g * KVST + kc * 8 + tg];
            uint32_t pa1 = Pu[(g + 8) * KVST + kc * 8 + tg];
            uint32_t pa2 = Pu[g * KVST + kc * 8 + tg + 4];
            uint32_t pa3 = Pu[(g + 8) * KVST + kc * 8 + tg + 4];
#pragma unroll
            for (int nt = 0; nt < 8; ++nt) {
                uint32_t b0 = Vu[(kc * 8 + tg) * KVST + nt * 8 + g];
                uint32_t b1 = Vu[(kc * 8 + tg + 4) * KVST + nt * 8 + g];
                mma_tf32(oacc[nt], pa0, pa1, pa2, pa3, b0, b1);
            }
        }
    }

    // ---- normalize + tf32-round + write to g_y ----
    const float inv_g = 1.f / l_g;
    const float inv_h = 1.f / l_h;
    const int h = bh & 15;
    float* yg = g_y + ((size_t)b * T_ + qrow_g) * D_ + h * 64;
    float* yh = g_y + ((size_t)b * T_ + qrow_h) * D_ + h * 64;
#pragma unroll
    for (int nt = 0; nt < 8; ++nt) {
        const int c = nt * 8 + 2 * tg;
        *(float2*)&yg[c] = make_float2(rna_tf32(oacc[nt][0] * inv_g),
                                       rna_tf32(oacc[nt][1] * inv_g));
        *(float2*)&yh[c] = make_float2(rna_tf32(oacc[nt][2] * inv_h),
                                       rna_tf32(oacc[nt][3] * inv_h));
    }
}

// ---------------------------------------------------------------------------
extern "C" void kernel_launch(void* const* d_in, const int* in_sizes, int n_in,
                              void* d_out, int out_size)
{
    const float* x   = (const float*)d_in[0];
    const int* amask = (const int*)d_in[1];
    const float* Wq  = (const float*)d_in[2];
    const float* bq  = (const float*)d_in[3];
    const float* Wk  = (const float*)d_in[4];
    const float* bk  = (const float*)d_in[5];
    const float* Wv  = (const float*)d_in[6];
    const float* bv  = (const float*)d_in[7];
    const float* Wo  = (const float*)d_in[8];
    const float* bo  = (const float*)d_in[9];
    float* out = (float*)d_out;

    static bool attr_set = false;
    if (!attr_set) {
        cudaFuncSetAttribute(mma_qkv, cudaFuncAttributeMaxDynamicSharedMemorySize, GSMEM_SZ);
        cudaFuncSetAttribute(mma_out, cudaFuncAttributeMaxDynamicSharedMemorySize, GSMEM_SZ);
        cudaFuncSetAttribute(attn_mma_kernel, cudaFuncAttributeMaxDynamicSharedMemorySize, ASMEM_SZ);
        attr_set = true;
    }

    // Prep: round x; transpose+round weights
    round_x_kernel<<<(M_ * D_ / 4) / 256, 256>>>(x);
    transpose_w_kernel<<<dim3(32, 32, 4), 256>>>(Wq, Wk, Wv, Wo);

    // QKV projections (mma.sync tf32)
    mma_qkv<<<dim3(D_ / 128, M_ / 128, 3), 256, GSMEM_SZ>>>(bq, bk, bv);

    // RoPE (tf32-rounded outputs)
    dim3 gr((B_ * H_ * T_ * 32) / 256, 1, 2);
    rope_kernel<<<gr, 256>>>();

    // Tensor-core flash attention
    attn_mma_kernel<<<dim3(T_ / 64, B_ * H_), 128, ASMEM_SZ>>>(amask);

    // Output projection (mma.sync tf32)
    mma_out<<<dim3(D_ / 128, M_ / 128), 256, GSMEM_SZ>>>(bo, out);
}

// round 6
// speedup vs baseline: 7.6785x; 1.5772x over previous
#include <cuda_runtime.h>
#include <cuda_bf16.h>
#include <math.h>
#include <cstdint>

// Problem constants
#define B_  2
#define T_  2048
#define D_  1024
#define H_  16
#define HS_ 64
#define M_  (B_ * T_)        // 4096 rows for projections

// ---------------------------------------------------------------------------
// Scratch (device globals; no allocation allowed)
// ---------------------------------------------------------------------------
__device__ float g_q[B_ * H_ * T_ * HS_];   // [B,H,T,HS] (tf32-rounded after rope)
__device__ float g_k[B_ * H_ * T_ * HS_];
__device__ float g_v[B_ * H_ * T_ * HS_];   // tf32-rounded at qkv epilogue
__device__ float g_y[B_ * T_ * D_];         // [B,T,H*HS] tf32-rounded by attn epilogue
__device__ float g_xt[M_ * D_];             // x, tf32-rounded
__device__ float g_wt[4 * D_ * D_];         // Wq,Wk,Wv,Wo transposed [N][K], tf32-rounded

// ---------------------------------------------------------------------------
// Helpers
// ---------------------------------------------------------------------------
__device__ __forceinline__ uint32_t smem_to_u32(const void* p) {
    uint32_t a;
    asm("{ .reg .u64 t; cvta.to.shared.u64 t, %1; cvt.u32.u64 %0, t; }" : "=r"(a) : "l"(p));
    return a;
}
__device__ __forceinline__ float rna_tf32(float v) {
    float r;
    asm("cvt.rna.tf32.f32 %0, %1;" : "=f"(r) : "f"(v));
    return r;
}
__device__ __forceinline__ void cp_async16(uint32_t saddr, const void* gptr) {
    asm volatile("cp.async.ca.shared.global [%0], [%1], 16;" :: "r"(saddr), "l"(gptr) : "memory");
}
__device__ __forceinline__ void cp_commit() {
    asm volatile("cp.async.commit_group;" ::: "memory");
}
__device__ __forceinline__ void cp_wait0() {
    asm volatile("cp.async.wait_group 0;" ::: "memory");
}
__device__ __forceinline__ void cp_wait1() {
    asm volatile("cp.async.wait_group 1;" ::: "memory");
}
__device__ __forceinline__ void cp_wait2() {
    asm volatile("cp.async.wait_group 2;" ::: "memory");
}

// mma.sync m16n8k8 tf32 (row.col), D += A*B
__device__ __forceinline__ void mma_tf32(float* d, uint32_t a0, uint32_t a1, uint32_t a2,
                                         uint32_t a3, uint32_t b0, uint32_t b1) {
    asm volatile(
        "mma.sync.aligned.m16n8k8.row.col.f32.tf32.tf32.f32 "
        "{%0,%1,%2,%3}, {%4,%5,%6,%7}, {%8,%9}, {%0,%1,%2,%3};"
        : "+f"(d[0]), "+f"(d[1]), "+f"(d[2]), "+f"(d[3])
        : "r"(a0), "r"(a1), "r"(a2), "r"(a3), "r"(b0), "r"(b1));
}

// ---------------------------------------------------------------------------
// tf32 mma.sync GEMM core (projections) — unchanged from R5.
// ---------------------------------------------------------------------------
#define BKC     32
#define AST     36
#define BUF_FL  (128 * AST)
#define GSMEM_SZ (2 * 2 * BUF_FL * 4)       // 73728 bytes

__device__ __forceinline__ void gemm_load_chunk(const float* __restrict__ A,
                                                const float* __restrict__ Bt,
                                                uint32_t smem_base, int buf,
                                                int m0, int n0, int k0, int tid)
{
#pragma unroll
    for (int i = 0; i < 4; ++i) {
        int f4  = tid + i * 256;
        int row = f4 >> 3;
        int cg  = f4 & 7;
        uint32_t dst = smem_base + ((buf * 2 + 0) * BUF_FL + row * AST + cg * 4) * 4;
        cp_async16(dst, &A[(size_t)(m0 + row) * D_ + k0 + cg * 4]);
    }
#pragma unroll
    for (int i = 0; i < 4; ++i) {
        int f4  = tid + i * 256;
        int row = f4 >> 3;
        int cg  = f4 & 7;
        uint32_t dst = smem_base + ((buf * 2 + 1) * BUF_FL + row * AST + cg * 4) * 4;
        cp_async16(dst, &Bt[(size_t)(n0 + row) * D_ + k0 + cg * 4]);
    }
    cp_commit();
}

__device__ __forceinline__ void gemm_compute_chunk(const uint32_t* __restrict__ smem_u,
                                                   int buf, int wm, int wn,
                                                   int g, int tg, float acc[2][8][4])
{
    const uint32_t* As = smem_u + (buf * 2 + 0) * BUF_FL;
    const uint32_t* Bs = smem_u + (buf * 2 + 1) * BUF_FL;
    const int mb = wm * 32;
    const int nb = wn * 64;

#pragma unroll
    for (int ks = 0; ks < 4; ++ks) {
        const int k0 = ks * 8;
        uint32_t a[2][4];
#pragma unroll
        for (int mt = 0; mt < 2; ++mt) {
            const uint32_t* ap = As + (mb + mt * 16 + g) * AST + k0 + tg;
            a[mt][0] = ap[0];
            a[mt][1] = ap[8 * AST];
            a[mt][2] = ap[4];
            a[mt][3] = ap[8 * AST + 4];
        }
        uint32_t b[8][2];
#pragma unroll
        for (int nt = 0; nt < 8; ++nt) {
            const uint32_t* bp = Bs + (nb + nt * 8 + g) * AST + k0 + tg;
            b[nt][0] = bp[0];
            b[nt][1] = bp[4];
        }
#pragma unroll
        for (int mt = 0; mt < 2; ++mt)
#pragma unroll
            for (int nt = 0; nt < 8; ++nt)
                mma_tf32(acc[mt][nt], a[mt][0], a[mt][1], a[mt][2], a[mt][3],
                         b[nt][0], b[nt][1]);
    }
}

__device__ __forceinline__ void gemm_main(const float* __restrict__ A,
                                          const float* __restrict__ Bt,
                                          uint32_t smem_base, const uint32_t* smem_u,
                                          int m0, int n0, int tid,
                                          int wm, int wn, int g, int tg,
                                          float acc[2][8][4])
{
#pragma unroll
    for (int mt = 0; mt < 2; ++mt)
#pragma unroll
        for (int nt = 0; nt < 8; ++nt)
#pragma unroll
            for (int i = 0; i < 4; ++i) acc[mt][nt][i] = 0.f;

    const int NCH = D_ / BKC;   // 32
    gemm_load_chunk(A, Bt, smem_base, 0, m0, n0, 0, tid);

    for (int c = 0; c < NCH; ++c) {
        if (c + 1 < NCH) {
            gemm_load_chunk(A, Bt, smem_base, (c + 1) & 1, m0, n0, (c + 1) * BKC, tid);
            cp_wait1();
        } else {
            cp_wait0();
        }
        __syncthreads();
        gemm_compute_chunk(smem_u, c & 1, wm, wn, g, tg, acc);
        __syncthreads();
    }
}

// QKV projection: A = g_xt, Bt = g_wt[z], epilogue writes [B,H,T,HS] + bias
__global__ void __launch_bounds__(256) mma_qkv(const float* __restrict__ bq,
                                               const float* __restrict__ bk,
                                               const float* __restrict__ bv)
{
    extern __shared__ float smem_f[];
    uint32_t smem_base = smem_to_u32(smem_f);
    const uint32_t* smem_u = (const uint32_t*)smem_f;

    const int z = blockIdx.z;
    const float* Bt   = g_wt + (size_t)z * (D_ * D_);
    const float* bias = (z == 0) ? bq : (z == 1) ? bk : bv;
    float* outp       = (z == 0) ? g_q : (z == 1) ? g_k : g_v;

    const int m0 = blockIdx.y * 128;
    const int n0 = blockIdx.x * 128;

    const int tid = threadIdx.x;
    const int wid = tid >> 5;
    const int lane = tid & 31;
    const int wm = wid & 3, wn = wid >> 2;
    const int g = lane >> 2, tg = lane & 3;

    float acc[2][8][4];
    gemm_main(g_xt, Bt, smem_base, smem_u, m0, n0, tid, wm, wn, g, tg, acc);

#pragma unroll
    for (int mt = 0; mt < 2; ++mt) {
#pragma unroll
        for (int half = 0; half < 2; ++half) {
            int m = m0 + wm * 32 + mt * 16 + g + half * 8;
            int b = m >> 11;
            int t = m & (T_ - 1);
#pragma unroll
            for (int nt = 0; nt < 8; ++nt) {
                int n = n0 + wn * 64 + nt * 8 + 2 * tg;
                int h = n >> 6;
                int d = n & 63;
                float v0 = acc[mt][nt][half * 2 + 0] + bias[n];
                float v1 = acc[mt][nt][half * 2 + 1] + bias[n + 1];
                if (z == 2) { v0 = rna_tf32(v0); v1 = rna_tf32(v1); }  // V feeds PV mma
                float* dst = outp + (((size_t)(b * H_ + h)) * T_ + t) * HS_ + d;
                *(float2*)dst = make_float2(v0, v1);
            }
        }
    }
}

// Output projection: A = g_y, Bt = g_wt[3], epilogue row-major + bias
__global__ void __launch_bounds__(256) mma_out(const float* __restrict__ bo,
                                               float* __restrict__ C)
{
    extern __shared__ float smem_f[];
    uint32_t smem_base = smem_to_u32(smem_f);
    const uint32_t* smem_u = (const uint32_t*)smem_f;

    const int m0 = blockIdx.y * 128;
    const int n0 = blockIdx.x * 128;

    const int tid = threadIdx.x;
    const int wid = tid >> 5;
    const int lane = tid & 31;
    const int wm = wid & 3, wn = wid >> 2;
    const int g = lane >> 2, tg = lane & 3;

    float acc[2][8][4];
    gemm_main(g_y, g_wt + (size_t)3 * (D_ * D_), smem_base, smem_u,
              m0, n0, tid, wm, wn, g, tg, acc);

#pragma unroll
    for (int mt = 0; mt < 2; ++mt) {
#pragma unroll
        for (int half = 0; half < 2; ++half) {
            int m = m0 + wm * 32 + mt * 16 + g + half * 8;
#pragma unroll
            for (int nt = 0; nt < 8; ++nt) {
                int n = n0 + wn * 64 + nt * 8 + 2 * tg;
                float v0 = acc[mt][nt][half * 2 + 0] + bo[n];
                float v1 = acc[mt][nt][half * 2 + 1] + bo[n + 1];
                *(float2*)&C[(size_t)m * D_ + n] = make_float2(v0, v1);
            }
        }
    }
}

// ---------------------------------------------------------------------------
// Prep kernels
// ---------------------------------------------------------------------------
__global__ void __launch_bounds__(256) round_x_kernel(const float* __restrict__ x)
{
    int i = blockIdx.x * 256 + threadIdx.x;
    float4 v = ((const float4*)x)[i];
    v.x = rna_tf32(v.x); v.y = rna_tf32(v.y);
    v.z = rna_tf32(v.z); v.w = rna_tf32(v.w);
    ((float4*)g_xt)[i] = v;
}

__global__ void __launch_bounds__(256) transpose_w_kernel(
    const float* __restrict__ Wq, const float* __restrict__ Wk,
    const float* __restrict__ Wv, const float* __restrict__ Wo)
{
    __shared__ float t[32][33];
    const int z = blockIdx.z;
    const float* W = (z == 0) ? Wq : (z == 1) ? Wk : (z == 2) ? Wv : Wo;
    float* out = g_wt + (size_t)z * (D_ * D_);

    const int x0 = blockIdx.x * 32;
    const int y0 = blockIdx.y * 32;
    const int tx = threadIdx.x & 31;
    const int ty = threadIdx.x >> 5;

#pragma unroll
    for (int i = 0; i < 4; ++i)
        t[ty + 8 * i][tx] = W[(size_t)(y0 + ty + 8 * i) * D_ + x0 + tx];
    __syncthreads();
#pragma unroll
    for (int i = 0; i < 4; ++i)
        out[(size_t)(x0 + ty + 8 * i) * D_ + y0 + tx] = rna_tf32(t[tx][ty + 8 * i]);
}

// ---------------------------------------------------------------------------
// RoPE in-place on g_q / g_k, output tf32-rounded (feeds QK^T mma)
// ---------------------------------------------------------------------------
__global__ void __launch_bounds__(256) rope_kernel()
{
    int idx = blockIdx.x * blockDim.x + threadIdx.x;
    float* arr = (blockIdx.z == 0) ? g_q : g_k;
    int i  = idx & 31;
    int t  = (idx >> 5) & (T_ - 1);
    int bh = idx >> 16;

    float invf = exp2f((float)i * -0.41524101186091056f);
    float ang = (float)t * invf;
    float s, c;
    sincosf(ang, &s, &c);

    float* p = arr + ((size_t)bh * T_ + t) * HS_;
    float x1 = p[i];
    float x2 = p[i + 32];
    p[i]      = rna_tf32(x1 * c - x2 * s);
    p[i + 32] = rna_tf32(x2 * c + x1 * s);
}

// ---------------------------------------------------------------------------
// Tensor-core flash attention, cp.async pipelined.
// CTA: 128 threads = 4 warps; 64 q-rows per CTA (16 per warp); kv tiles of 64.
// SMEM (floats): Kbuf[2][64*68], Vs[64*68], Ps[4][16*68] (also Q staging),
//                mskI int[2][64].
// Pipeline: K+msk double-buffered (issued 1 tile ahead); V issued at tile
// start, awaited after S+softmax (latency hidden behind QK^T + exp).
// ---------------------------------------------------------------------------
#define KVST 68
#define AKV  (64 * KVST)                 // 4352 floats per tile
#define OFF_V  (2 * AKV)
#define OFF_P  (3 * AKV)
#define OFF_MSK (4 * AKV)                // int[2][64] stored here
#define ASMEM_FL (4 * AKV + 128)
#define ASMEM_SZ (ASMEM_FL * 4)          // 70144 bytes

__global__ void __launch_bounds__(128) attn_mma_kernel(const int* __restrict__ amask)
{
    extern __shared__ float sm[];
    float* Vs  = sm + OFF_V;
    float* Ps  = sm + OFF_P;
    int*   mskI = (int*)(sm + OFF_MSK);   // [2][64]

    const uint32_t smem_base = smem_to_u32(sm);

    const int bh = blockIdx.y;
    const int b  = bh >> 4;
    const int qi = (int)(gridDim.x - 1) - (int)blockIdx.x;   // big tiles first
    const int q0 = qi << 6;

    const int tid  = threadIdx.x;
    const int wid  = tid >> 5;
    const int lane = tid & 31;
    const int g  = lane >> 2, tg = lane & 3;
    const int mb = wid * 16;

    const float* qbase = g_q + ((size_t)bh * T_ + q0) * HS_;
    const float* kbase = g_k + (size_t)bh * T_ * HS_;
    const float* vbase = g_v + (size_t)bh * T_ * HS_;
    const int* mptr = amask + b * T_;

    // ---- stage Q tile into Ps (64 rows x 64 cols, stride KVST) ----
#pragma unroll
    for (int i = 0; i < 8; ++i) {
        int f4 = tid + i * 128;
        int row = f4 >> 4, cg = f4 & 15;
        *(float4*)&Ps[row * KVST + cg * 4] = ((const float4*)qbase)[f4];
    }
    __syncthreads();
    uint32_t qa[8][4];
    {
        const uint32_t* Pu0 = (const uint32_t*)Ps;
#pragma unroll
        for (int kc = 0; kc < 8; ++kc) {
            qa[kc][0] = Pu0[(mb + g) * KVST + kc * 8 + tg];
            qa[kc][1] = Pu0[(mb + g + 8) * KVST + kc * 8 + tg];
            qa[kc][2] = Pu0[(mb + g) * KVST + kc * 8 + tg + 4];
            qa[kc][3] = Pu0[(mb + g + 8) * KVST + kc * 8 + tg + 4];
        }
    }

    float m_g = -1e30f, m_h = -1e30f, l_g = 0.f, l_h = 0.f;
    float oacc[8][4];
#pragma unroll
    for (int nt = 0; nt < 8; ++nt)
#pragma unroll
        for (int i = 0; i < 4; ++i) oacc[nt][i] = 0.f;

    const int qrow_g = q0 + mb + g;
    const int qrow_h = qrow_g + 8;
    float* Pw = Ps + wid * 16 * KVST;
    const uint32_t* Vu = (const uint32_t*)Vs;
    const uint32_t* Pu = (const uint32_t*)Pw;

    // ---- prologue: K(0) + msk(0) ----
    {
        const float4* ksrc = (const float4*)kbase;
#pragma unroll
        for (int i = 0; i < 8; ++i) {
            int f4 = tid + i * 128;
            int row = f4 >> 4, cg = f4 & 15;
            cp_async16(smem_base + (row * KVST + cg * 4) * 4, &ksrc[f4]);
        }
        if (tid < 16) cp_async16(smem_base + (OFF_MSK + tid * 4) * 4, &mptr[tid * 4]);
        cp_commit();
    }

    for (int kt = 0; kt <= qi; ++kt) {
        const int k0t = kt << 6;
        const int buf = kt & 1;

        __syncthreads();   // (a) previous tile fully consumed (V, K, P safe)

        // issue V(kt) into single buffer
        {
            const float4* vsrc = (const float4*)(vbase + (size_t)k0t * HS_);
#pragma unroll
            for (int i = 0; i < 8; ++i) {
                int f4 = tid + i * 128;
                int row = f4 >> 4, cg = f4 & 15;
                cp_async16(smem_base + (OFF_V + row * KVST + cg * 4) * 4, &vsrc[f4]);
            }
            cp_commit();
        }
        // issue K(kt+1) + msk(kt+1)
        if (kt < qi) {
            const float4* ksrc = (const float4*)(kbase + (size_t)(k0t + 64) * HS_);
            const uint32_t kdst = smem_base + ((1 - buf) * AKV) * 4;
#pragma unroll
            for (int i = 0; i < 8; ++i) {
                int f4 = tid + i * 128;
                int row = f4 >> 4, cg = f4 & 15;
                cp_async16(kdst + (row * KVST + cg * 4) * 4, &ksrc[f4]);
            }
            if (tid < 16)
                cp_async16(smem_base + (OFF_MSK + (1 - buf) * 64 + tid * 4) * 4,
                           &mptr[k0t + 64 + tid * 4]);
            cp_commit();
        }

        // wait for K(kt)+msk(kt): allow {V(kt), K(kt+1)} pending
        if (kt < qi) cp_wait2(); else cp_wait1();
        __syncthreads();   // (b) K visible

        const uint32_t* Ku = (const uint32_t*)(sm + buf * AKV);
        const int* mk = mskI + buf * 64;

        // ---- S = Q K^T ----
        float sacc[8][4];
#pragma unroll
        for (int nt = 0; nt < 8; ++nt)
#pragma unroll
            for (int i = 0; i < 4; ++i) sacc[nt][i] = 0.f;

#pragma unroll
        for (int kc = 0; kc < 8; ++kc) {
            uint32_t bfr[8][2];
#pragma unroll
            for (int nt = 0; nt < 8; ++nt) {
                const uint32_t* bp = Ku + (nt * 8 + g) * KVST + kc * 8 + tg;
                bfr[nt][0] = bp[0];
                bfr[nt][1] = bp[4];
            }
#pragma unroll
            for (int nt = 0; nt < 8; ++nt)
                mma_tf32(sacc[nt], qa[kc][0], qa[kc][1], qa[kc][2], qa[kc][3],
                         bfr[nt][0], bfr[nt][1]);
        }

        // ---- scale + mask + row max ----
        float tmax_g = -1e30f, tmax_h = -1e30f;
#pragma unroll
        for (int nt = 0; nt < 8; ++nt) {
            const int c0 = nt * 8 + 2 * tg, c1 = c0 + 1;
            float mk0 = mk[c0] ? 0.f : -1e30f;
            float mk1 = mk[c1] ? 0.f : -1e30f;
            float s0 = fmaf(sacc[nt][0], 0.125f, mk0);
            float s1 = fmaf(sacc[nt][1], 0.125f, mk1);
            float s2 = fmaf(sacc[nt][2], 0.125f, mk0);
            float s3 = fmaf(sacc[nt][3], 0.125f, mk1);
            if (kt == qi) {
                if (k0t + c0 > qrow_g) s0 = -1e30f;
                if (k0t + c1 > qrow_g) s1 = -1e30f;
                if (k0t + c0 > qrow_h) s2 = -1e30f;
                if (k0t + c1 > qrow_h) s3 = -1e30f;
            }
            sacc[nt][0] = s0; sacc[nt][1] = s1; sacc[nt][2] = s2; sacc[nt][3] = s3;
            tmax_g = fmaxf(tmax_g, fmaxf(s0, s1));
            tmax_h = fmaxf(tmax_h, fmaxf(s2, s3));
        }
        tmax_g = fmaxf(tmax_g, __shfl_xor_sync(0xffffffffu, tmax_g, 1));
        tmax_g = fmaxf(tmax_g, __shfl_xor_sync(0xffffffffu, tmax_g, 2));
        tmax_h = fmaxf(tmax_h, __shfl_xor_sync(0xffffffffu, tmax_h, 1));
        tmax_h = fmaxf(tmax_h, __shfl_xor_sync(0xffffffffu, tmax_h, 2));

        const float mn_g = fmaxf(m_g, tmax_g);
        const float mn_h = fmaxf(m_h, tmax_h);
        const float corr_g = __expf(m_g - mn_g);
        const float corr_h = __expf(m_h - mn_h);
        m_g = mn_g; m_h = mn_h;

        // ---- exp + row sum + tf32-round P ----
        float rs_g = 0.f, rs_h = 0.f;
#pragma unroll
        for (int nt = 0; nt < 8; ++nt) {
            float p0 = __expf(sacc[nt][0] - mn_g);
            float p1 = __expf(sacc[nt][1] - mn_g);
            float p2 = __expf(sacc[nt][2] - mn_h);
            float p3 = __expf(sacc[nt][3] - mn_h);
            rs_g += p0 + p1;
            rs_h += p2 + p3;
            sacc[nt][0] = rna_tf32(p0); sacc[nt][1] = rna_tf32(p1);
            sacc[nt][2] = rna_tf32(p2); sacc[nt][3] = rna_tf32(p3);
        }
        rs_g += __shfl_xor_sync(0xffffffffu, rs_g, 1);
        rs_g += __shfl_xor_sync(0xffffffffu, rs_g, 2);
        rs_h += __shfl_xor_sync(0xffffffffu, rs_h, 1);
        rs_h += __shfl_xor_sync(0xffffffffu, rs_h, 2);
        l_g = l_g * corr_g + rs_g;
        l_h = l_h * corr_h + rs_h;

#pragma unroll
        for (int nt = 0; nt < 8; ++nt) {
            oacc[nt][0] *= corr_g; oacc[nt][1] *= corr_g;
            oacc[nt][2] *= corr_h; oacc[nt][3] *= corr_h;
        }

        // ---- P accumulator-layout -> A-fragment layout (warp-private smem) ----
        __syncwarp();
#pragma unroll
        for (int nt = 0; nt < 8; ++nt) {
            *(float2*)&Pw[g * KVST + nt * 8 + 2 * tg]       = make_float2(sacc[nt][0], sacc[nt][1]);
            *(float2*)&Pw[(g + 8) * KVST + nt * 8 + 2 * tg] = make_float2(sacc[nt][2], sacc[nt][3]);
        }
        __syncwarp();

        // wait for V(kt): allow {K(kt+1)} pending
        if (kt < qi) cp_wait1(); else cp_wait0();
        __syncthreads();   // (c) V visible

        // ---- O += P V ----
#pragma unroll
        for (int kc = 0; kc < 8; ++kc) {
            uint32_t pa0 = Pu[g * KVST + kc * 8 + tg];
            uint32_t pa1 = Pu[(g + 8) * KVST + kc * 8 + tg];
            uint32_t pa2 = Pu[g * KVST + kc * 8 + tg + 4];
            uint32_t pa3 = Pu[(g + 8) * KVST + kc * 8 + tg + 4];
#pragma unroll
            for (int nt = 0; nt < 8; ++nt) {
                uint32_t b0 = Vu[(kc * 8 + tg) * KVST + nt * 8 + g];
                uint32_t b1 = Vu[(kc * 8 + tg + 4) * KVST + nt * 8 + g];
                mma_tf32(oacc[nt], pa0, pa1, pa2, pa3, b0, b1);
            }
        }
    }

    // ---- normalize + tf32-round + write to g_y ----
    const float inv_g = 1.f / l_g;
    const float inv_h = 1.f / l_h;
    const int h = bh & 15;
    float* yg = g_y + ((size_t)b * T_ + qrow_g) * D_ + h * 64;
    float* yh = g_y + ((size_t)b * T_ + qrow_h) * D_ + h * 64;
#pragma unroll
    for (int nt = 0; nt < 8; ++nt) {
        const int c = nt * 8 + 2 * tg;
        *(float2*)&yg[c] = make_float2(rna_tf32(oacc[nt][0] * inv_g),
                                       rna_tf32(oacc[nt][1] * inv_g));
        *(float2*)&yh[c] = make_float2(rna_tf32(oacc[nt][2] * inv_h),
                                       rna_tf32(oacc[nt][3] * inv_h));
    }
}

// ---------------------------------------------------------------------------
extern "C" void kernel_launch(void* const* d_in, const int* in_sizes, int n_in,
                              void* d_out, int out_size)
{
    const float* x   = (const float*)d_in[0];
    const int* amask = (const int*)d_in[1];
    const float* Wq  = (const float*)d_in[2];
    const float* bq  = (const float*)d_in[3];
    const float* Wk  = (const float*)d_in[4];
    const float* bk  = (const float*)d_in[5];
    const float* Wv  = (const float*)d_in[6];
    const float* bv  = (const float*)d_in[7];
    const float* Wo  = (const float*)d_in[8];
    const float* bo  = (const float*)d_in[9];
    float* out = (float*)d_out;

    static bool attr_set = false;
    if (!attr_set) {
        cudaFuncSetAttribute(mma_qkv, cudaFuncAttributeMaxDynamicSharedMemorySize, GSMEM_SZ);
        cudaFuncSetAttribute(mma_out, cudaFuncAttributeMaxDynamicSharedMemorySize, GSMEM_SZ);
        cudaFuncSetAttribute(attn_mma_kernel, cudaFuncAttributeMaxDynamicSharedMemorySize, ASMEM_SZ);
        attr_set = true;
    }

    // Prep: round x; transpose+round weights
    round_x_kernel<<<(M_ * D_ / 4) / 256, 256>>>(x);
    transpose_w_kernel<<<dim3(32, 32, 4), 256>>>(Wq, Wk, Wv, Wo);

    // QKV projections (mma.sync tf32)
    mma_qkv<<<dim3(D_ / 128, M_ / 128, 3), 256, GSMEM_SZ>>>(bq, bk, bv);

    // RoPE (tf32-rounded outputs)
    dim3 gr((B_ * H_ * T_ * 32) / 256, 1, 2);
    rope_kernel<<<gr, 256>>>();

    // Tensor-core flash attention (pipelined)
    attn_mma_kernel<<<dim3(T_ / 64, B_ * H_), 128, ASMEM_SZ>>>(amask);

    // Output projection (mma.sync tf32)
    mma_out<<<dim3(D_ / 128, M_ / 128), 256, GSMEM_SZ>>>(bo, out);
}